// round 15
// baseline (speedup 1.0000x reference)
#include <cuda_runtime.h>
#include <cuda_fp16.h>
#include <cstdint>
#include <cstddef>

#define HID 128
#define C3  384
#define TT  512
#define BB  4096
#define INP 28

// 1.6 GB scratch: gx[t][b][c] in fp16, c = g*128+u (b_x folded into gru).
__device__ __align__(16) __half g_gx_lo[(size_t)256 * BB * C3];
__device__ __align__(16) __half g_gx_hi[(size_t)256 * BB * C3];

static __device__ __forceinline__ float sig1(float x) {
    float e = __expf(-x);
    return __fdividef(1.0f, 1.0f + e);
}
static __device__ __forceinline__ float tanh1(float x) {
    float e = __expf(2.0f * x);
    return 1.0f - __fdividef(2.0f, e + 1.0f);
}
static __device__ __forceinline__ uint32_t smem_u32(const void* p) {
    uint32_t a;
    asm("{ .reg .u64 t; cvta.to.shared.u64 t, %1; cvt.u32.u64 %0, t; }"
        : "=r"(a) : "l"(p));
    return a;
}
static __device__ __forceinline__ void ldsm4(uint32_t& r0, uint32_t& r1,
                                             uint32_t& r2, uint32_t& r3, uint32_t a) {
    asm volatile("ldmatrix.sync.aligned.m8n8.x4.shared.b16 {%0,%1,%2,%3}, [%4];"
                 : "=r"(r0), "=r"(r1), "=r"(r2), "=r"(r3) : "r"(a));
}
static __device__ __forceinline__ void ldsm4t(uint32_t& r0, uint32_t& r1,
                                              uint32_t& r2, uint32_t& r3, uint32_t a) {
    asm volatile("ldmatrix.sync.aligned.m8n8.x4.trans.shared.b16 {%0,%1,%2,%3}, [%4];"
                 : "=r"(r0), "=r"(r1), "=r"(r2), "=r"(r3) : "r"(a));
}
static __device__ __forceinline__ void mma16816(float* d,
        uint32_t a0, uint32_t a1, uint32_t a2, uint32_t a3,
        uint32_t b0, uint32_t b1) {
    asm volatile("mma.sync.aligned.m16n8k16.row.col.f32.f16.f16.f32 "
                 "{%0,%1,%2,%3},{%4,%5,%6,%7},{%8,%9},{%0,%1,%2,%3};"
                 : "+f"(d[0]), "+f"(d[1]), "+f"(d[2]), "+f"(d[3])
                 : "r"(a0), "r"(a1), "r"(a2), "r"(a3), "r"(b0), "r"(b1));
}

// ---------------------------------------------------------------------------
// Kernel A (HMMA): gx[t][b][c] = sum_k x[b][t][k] * w_x[k][c], fp16 output.
// CTA = (128 batch rows, 8 timesteps): w_x converted to smem ONCE per CTA.
// 2-term x split (xh*wh + xl*wh); output quantized to fp16 (iid noise,
// averaged by the contractive recurrence).
// ---------------------------------------------------------------------------
#define WSTR 392
#define XSTR 40
#define GSM_WH 0
#define GSM_XH (32 * WSTR * 2)                  // 25088
#define GSM_XL (GSM_XH + HID * XSTR * 2)        // 35328
#define GSM_TOT (GSM_XL + HID * XSTR * 2)       // 45568

__global__ void __launch_bounds__(256, 2)
gx_kernel(const float* __restrict__ x,
          const float* __restrict__ w_x) {
    extern __shared__ char smem[];
    __half* sWH = (__half*)(smem + GSM_WH);
    __half* sXH = (__half*)(smem + GSM_XH);
    __half* sXL = (__half*)(smem + GSM_XL);
    const uint32_t sb = smem_u32(smem);

    const int tid = threadIdx.x;
    const int w   = tid >> 5;
    const int L   = tid & 31;
    const int b0  = blockIdx.x * 128;

    // ---- w_x -> fp16 smem, once per CTA ----
    for (int idx = tid; idx < 3 * INP * HID; idx += 256) {
        int g = idx / (INP * HID);
        int k = (idx / HID) % INP;
        int u = idx & 127;
        sWH[k * WSTR + g * HID + u] = __float2half_rn(w_x[idx]);
    }
    for (int idx = tid; idx < 4 * C3; idx += 256) {
        int k = 28 + idx / C3, c = idx % C3;
        sWH[k * WSTR + c] = __ushort_as_half(0);
    }
    // x k-pad columns zeroed once (never overwritten by per-t fills)
    for (int idx = tid; idx < 128 * 4; idx += 256) {
        int r = idx >> 2, k = 28 + (idx & 3);
        sXH[r * XSTR + k] = __ushort_as_half(0);
        sXL[r * XSTR + k] = __ushort_as_half(0);
    }

    const uint32_t lrow = (L & 7) + ((L >> 3) & 1) * 8;
    const uint32_t lcol = (L >> 4) * 8;
    const uint32_t aXH = sb + GSM_XH + (uint32_t)((16 * w + lrow) * XSTR + lcol) * 2;
    const uint32_t aXL = sb + GSM_XL + (uint32_t)((16 * w + lrow) * XSTR + lcol) * 2;
    const uint32_t bWH = sb + GSM_WH + (uint32_t)(lrow * WSTR + lcol) * 2;

    const int rA = 16 * w + (L >> 2);
    const int cq = 2 * (L & 3);

    for (int tt = 0; tt < 8; ++tt) {
        const int t = blockIdx.y * 8 + tt;

        __syncthreads();   // prior iteration's smem reads done (covers w fill on tt=0)
        for (int idx = tid; idx < 128 * 7; idx += 256) {
            int r = idx / 7, f = idx % 7;
            float4 v = *(const float4*)(x + ((size_t)(b0 + r) * TT + t) * INP + 4 * f);
            float vs[4] = {v.x, v.y, v.z, v.w};
#pragma unroll
            for (int j = 0; j < 4; ++j) {
                __half hi = __float2half_rn(vs[j]);
                __half lo = __float2half_rn(vs[j] - __half2float(hi));
                sXH[r * XSTR + 4 * f + j] = hi;
                sXL[r * XSTR + 4 * f + j] = lo;
            }
        }
        __syncthreads();

        uint32_t axh[2][4], axl[2][4];
#pragma unroll
        for (int kt = 0; kt < 2; ++kt) {
            ldsm4(axh[kt][0], axh[kt][1], axh[kt][2], axh[kt][3], aXH + kt * 32);
            ldsm4(axl[kt][0], axl[kt][1], axl[kt][2], axl[kt][3], aXL + kt * 32);
        }

        __half* gxo = ((t < 256) ? g_gx_lo : g_gx_hi) + (size_t)(t & 255) * BB * C3;

#pragma unroll 1
        for (int ch = 0; ch < 6; ++ch) {
            float acc[8][4];
#pragma unroll
            for (int nb = 0; nb < 8; ++nb)
#pragma unroll
                for (int i = 0; i < 4; ++i) acc[nb][i] = 0.0f;

#pragma unroll
            for (int kt = 0; kt < 2; ++kt) {
#pragma unroll
                for (int grp = 0; grp < 4; ++grp) {
                    uint32_t off = (uint32_t)(kt * 16 * WSTR + ch * 64 + grp * 16) * 2;
                    uint32_t h0, h1, h2, h3;
                    ldsm4t(h0, h1, h2, h3, bWH + off);
                    float* a0 = acc[2 * grp];
                    float* a1 = acc[2 * grp + 1];
                    mma16816(a0, axh[kt][0], axh[kt][1], axh[kt][2], axh[kt][3], h0, h1);
                    mma16816(a0, axl[kt][0], axl[kt][1], axl[kt][2], axl[kt][3], h0, h1);
                    mma16816(a1, axh[kt][0], axh[kt][1], axh[kt][2], axh[kt][3], h2, h3);
                    mma16816(a1, axl[kt][0], axl[kt][1], axl[kt][2], axl[kt][3], h2, h3);
                }
            }

#pragma unroll
            for (int nb = 0; nb < 8; ++nb) {
                int c = ch * 64 + nb * 8 + cq;
                *(__half2*)(gxo + (size_t)(b0 + rA) * C3 + c) =
                    __floats2half2_rn(acc[nb][0], acc[nb][1]);
                *(__half2*)(gxo + (size_t)(b0 + rA + 8) * C3 + c) =
                    __floats2half2_rn(acc[nb][2], acc[nb][3]);
            }
        }
    }
}

// ---------------------------------------------------------------------------
// Kernel B: GRU on HMMA, 2-term split (wh*hh + wh*hl), batch-split software
// pipeline (mma0 / gates1 / bar / mma1 / gates0 / bar). gx read as fp16.
// 128 CTAs x 32 rows, 256 threads / 8 warps.
// ---------------------------------------------------------------------------
#define ASTR 136
#define AMAT (HID * ASTR)
#define BSTR 40
#define SM_B0 (3 * AMAT * 2)                    // 104448
#define SM_B1 (SM_B0 + HID * BSTR * 2)          // 114688
#define SM_TOT (SM_B1 + HID * BSTR * 2)         // 124928

__global__ void __launch_bounds__(256, 1)
gru_kernel(const float* __restrict__ w_h,
           const float* __restrict__ b_h,
           const float* __restrict__ b_x,
           const float* __restrict__ fc_w,
           const float* __restrict__ fc_b,
           float* __restrict__ out) {
    extern __shared__ char smem[];
    __half* sA = (__half*)smem;
    __half* sBhh = (__half*)(smem + SM_B0);
    __half* sBhl = (__half*)(smem + SM_B1);
    const uint32_t sb = smem_u32(smem);

    const int tid = threadIdx.x;
    const int w   = tid >> 5;
    const int L   = tid & 31;
    const int row0 = blockIdx.x * 32;
    const int uBase = 16 * w + (L >> 2);

    for (int g = 0; g < 3; ++g) {
        __half* ah = sA + g * AMAT;
        const float* wg = w_h + (size_t)g * HID * HID;
        for (int idx = tid; idx < HID * HID; idx += 256) {
            int k = idx >> 7, u = idx & 127;
            ah[u * ASTR + k] = __float2half_rn(wg[idx]);
        }
    }
    for (int i = tid; i < HID * BSTR; i += 256) {
        sBhh[i] = __ushort_as_half(0);
        sBhl[i] = __ushort_as_half(0);
    }
    __syncthreads();

    const uint32_t lrow = (L & 7) + ((L >> 3) & 1) * 8;
    const uint32_t lcol = (L >> 4) * 8;
    uint32_t aAddr[3];
#pragma unroll
    for (int m = 0; m < 3; ++m)
        aAddr[m] = sb + (uint32_t)(m * AMAT + (16 * w + lrow) * ASTR + lcol) * 2;
    const uint32_t bAddrHH = sb + SM_B0 + (lrow * BSTR + lcol) * 2;
    const uint32_t bAddrHL = sb + SM_B1 + (lrow * BSTR + lcol) * 2;

    float bhr[2], bhz[2], bhn[2], bxn[2];
#pragma unroll
    for (int ui = 0; ui < 2; ++ui) {
        int u = uBase + 8 * ui;
        bhr[ui] = b_h[u]           + b_x[u];
        bhz[ui] = b_h[HID + u]     + b_x[HID + u];
        bhn[ui] = b_h[2 * HID + u];
        bxn[ui] = b_x[2 * HID + u];
    }

    float hold0[2][4], hold1[2][4];
#pragma unroll
    for (int ui = 0; ui < 2; ++ui)
#pragma unroll
        for (int e = 0; e < 4; ++e) { hold0[ui][e] = 0.0f; hold1[ui][e] = 0.0f; }

    float acc0[3][2][4], acc1[3][2][4];
    float pg0[3][2][4], pg1[3][2][4];

#define LOAD_PG(PG, T, HF) do {                                               \
    const __half* _b = ((T) < 256) ? g_gx_lo : g_gx_hi;                       \
    const __half* _gp = _b + (size_t)((T) & 255) * BB * C3;                   \
    _Pragma("unroll")                                                         \
    for (int g = 0; g < 3; ++g)                                               \
        _Pragma("unroll")                                                     \
        for (int ui = 0; ui < 2; ++ui) {                                      \
            int u = uBase + 8 * ui;                                           \
            _Pragma("unroll")                                                 \
            for (int e = 0; e < 4; ++e) {                                     \
                int b = 16 * (HF) + 8 * (e >> 1) + 2 * (L & 3) + (e & 1);     \
                PG[g][ui][e] = __half2float(                                  \
                    __ldg(_gp + (size_t)(row0 + b) * C3 + g * HID + u));      \
            }                                                                 \
        }                                                                     \
} while (0)

#define MMA_PHASE(ACC, HF) do {                                               \
    _Pragma("unroll")                                                         \
    for (int g = 0; g < 3; ++g)                                               \
        _Pragma("unroll")                                                     \
        for (int nb = 0; nb < 2; ++nb)                                        \
            _Pragma("unroll")                                                 \
            for (int i = 0; i < 4; ++i) ACC[g][nb][i] = 0.0f;                 \
    _Pragma("unroll")                                                         \
    for (int kt = 0; kt < 8; ++kt) {                                          \
        uint32_t bh0, bh1, bh2, bh3, bl0, bl1, bl2, bl3;                      \
        uint32_t boff = (uint32_t)(kt * 16 * BSTR * 2) + (HF) * 32;           \
        ldsm4t(bh0, bh1, bh2, bh3, bAddrHH + boff);                           \
        ldsm4t(bl0, bl1, bl2, bl3, bAddrHL + boff);                           \
        _Pragma("unroll")                                                     \
        for (int g = 0; g < 3; ++g) {                                         \
            uint32_t ah0, ah1, ah2, ah3;                                      \
            ldsm4(ah0, ah1, ah2, ah3, aAddr[g] + kt * 32);                    \
            mma16816(ACC[g][0], ah0, ah1, ah2, ah3, bh0, bh1);                \
            mma16816(ACC[g][0], ah0, ah1, ah2, ah3, bl0, bl1);                \
            mma16816(ACC[g][1], ah0, ah1, ah2, ah3, bh2, bh3);                \
            mma16816(ACC[g][1], ah0, ah1, ah2, ah3, bl2, bl3);                \
        }                                                                     \
    }                                                                         \
} while (0)

#define GATES_PHASE(ACC, PG, HOLD, HF, WRITE_B) do {                          \
    _Pragma("unroll")                                                         \
    for (int ui = 0; ui < 2; ++ui) {                                          \
        int u = uBase + 8 * ui;                                               \
        _Pragma("unroll")                                                     \
        for (int nb = 0; nb < 2; ++nb) {                                      \
            float hv[2];                                                      \
            _Pragma("unroll")                                                 \
            for (int q = 0; q < 2; ++q) {                                     \
                int e = 2 * nb + q;                                           \
                float ar = ACC[0][nb][2 * ui + q] + PG[0][ui][e] + bhr[ui];   \
                float az = ACC[1][nb][2 * ui + q] + PG[1][ui][e] + bhz[ui];   \
                float an = ACC[2][nb][2 * ui + q] + bhn[ui];                  \
                float rr = sig1(ar);                                          \
                float zz = sig1(az);                                          \
                float nn = tanh1(PG[2][ui][e] + bxn[ui] + rr * an);           \
                float h  = nn + zz * (HOLD[ui][e] - nn);                      \
                HOLD[ui][e] = h;                                              \
                hv[q] = h;                                                    \
            }                                                                 \
            if (WRITE_B) {                                                    \
                int b = 16 * (HF) + 8 * nb + 2 * (L & 3);                     \
                __half h0 = __float2half_rn(hv[0]);                           \
                __half h1 = __float2half_rn(hv[1]);                           \
                __half l0 = __float2half_rn(hv[0] - __half2float(h0));        \
                __half l1 = __float2half_rn(hv[1] - __half2float(h1));        \
                *(__half2*)(sBhh + u * BSTR + b) = __halves2half2(h0, h1);    \
                *(__half2*)(sBhl + u * BSTR + b) = __halves2half2(l0, l1);    \
            }                                                                 \
        }                                                                     \
    }                                                                         \
} while (0)

    LOAD_PG(pg0, 0, 0);

    for (int t = 0; t < TT; ++t) {
        MMA_PHASE(acc0, 0);                    // reads B0(t)
        if (t > 0) GATES_PHASE(acc1, pg1, hold1, 1, 1);   // writes B1(t)
        LOAD_PG(pg1, t, 1);
        __syncthreads();
        MMA_PHASE(acc1, 1);                    // reads B1(t)
        GATES_PHASE(acc0, pg0, hold0, 0, 1);   // writes B0(t+1)
        if (t + 1 < TT) LOAD_PG(pg0, t + 1, 0);
        __syncthreads();
    }
    GATES_PHASE(acc1, pg1, hold1, 1, 0);

    // ---- FC epilogue ----
    float* sH  = (float*)smem;
    float* sFW = (float*)smem + HID * 33;
#pragma unroll
    for (int ui = 0; ui < 2; ++ui) {
        int u = uBase + 8 * ui;
#pragma unroll
        for (int e = 0; e < 4; ++e) {
            int bq = 8 * (e >> 1) + 2 * (L & 3) + (e & 1);
            sH[u * 33 + bq]      = hold0[ui][e];
            sH[u * 33 + 16 + bq] = hold1[ui][e];
        }
    }
    for (int i = tid; i < HID * 10; i += 256) sFW[i] = fc_w[i];
    __syncthreads();
    for (int i = tid; i < 32 * 10; i += 256) {
        int lr = i / 10, col = i % 10;
        float s = fc_b[col];
#pragma unroll 8
        for (int uu = 0; uu < HID; ++uu)
            s += sH[uu * 33 + lr] * sFW[uu * 10 + col];
        out[(size_t)(row0 + lr) * 10 + col] = s;
    }
#undef LOAD_PG
#undef MMA_PHASE
#undef GATES_PHASE
}

extern "C" void kernel_launch(void* const* d_in, const int* in_sizes, int n_in,
                              void* d_out, int out_size) {
    const float* x    = (const float*)d_in[0];
    const float* w_x  = (const float*)d_in[1];
    const float* b_x  = (const float*)d_in[2];
    const float* w_h  = (const float*)d_in[3];
    const float* b_h  = (const float*)d_in[4];
    const float* fc_w = (const float*)d_in[5];
    const float* fc_b = (const float*)d_in[6];
    float* out = (float*)d_out;

    cudaFuncSetAttribute(gx_kernel,  cudaFuncAttributeMaxDynamicSharedMemorySize, GSM_TOT);
    cudaFuncSetAttribute(gru_kernel, cudaFuncAttributeMaxDynamicSharedMemorySize, SM_TOT);

    gx_kernel<<<dim3(32, TT / 8), 256, GSM_TOT>>>(x, w_x);
    gru_kernel<<<128, 256, SM_TOT>>>(w_h, b_h, b_x, fc_w, fc_b, out);
}

// round 16
// speedup vs baseline: 1.1617x; 1.1617x over previous
#include <cuda_runtime.h>
#include <cuda_fp16.h>
#include <cstdint>
#include <cstddef>

#define HID 128
#define C3  384
#define TT  512
#define BB  4096
#define INP 28

// 3.2 GB scratch: gx[t][b][c] fp32, c = g*128+u (b_x folded into gru biases).
__device__ __align__(16) float g_gx_lo[(size_t)256 * BB * C3];
__device__ __align__(16) float g_gx_hi[(size_t)256 * BB * C3];

static __device__ __forceinline__ float sig1(float x) {
    float e = __expf(-x);
    return __fdividef(1.0f, 1.0f + e);
}
static __device__ __forceinline__ float tanh1(float x) {
    float e = __expf(2.0f * x);
    return 1.0f - __fdividef(2.0f, e + 1.0f);
}
static __device__ __forceinline__ uint32_t smem_u32(const void* p) {
    uint32_t a;
    asm("{ .reg .u64 t; cvta.to.shared.u64 t, %1; cvt.u32.u64 %0, t; }"
        : "=r"(a) : "l"(p));
    return a;
}
static __device__ __forceinline__ void ldsm4(uint32_t& r0, uint32_t& r1,
                                             uint32_t& r2, uint32_t& r3, uint32_t a) {
    asm volatile("ldmatrix.sync.aligned.m8n8.x4.shared.b16 {%0,%1,%2,%3}, [%4];"
                 : "=r"(r0), "=r"(r1), "=r"(r2), "=r"(r3) : "r"(a));
}
static __device__ __forceinline__ void ldsm4t(uint32_t& r0, uint32_t& r1,
                                              uint32_t& r2, uint32_t& r3, uint32_t a) {
    asm volatile("ldmatrix.sync.aligned.m8n8.x4.trans.shared.b16 {%0,%1,%2,%3}, [%4];"
                 : "=r"(r0), "=r"(r1), "=r"(r2), "=r"(r3) : "r"(a));
}
static __device__ __forceinline__ void mma16816(float* d,
        uint32_t a0, uint32_t a1, uint32_t a2, uint32_t a3,
        uint32_t b0, uint32_t b1) {
    asm volatile("mma.sync.aligned.m16n8k16.row.col.f32.f16.f16.f32 "
                 "{%0,%1,%2,%3},{%4,%5,%6,%7},{%8,%9},{%0,%1,%2,%3};"
                 : "+f"(d[0]), "+f"(d[1]), "+f"(d[2]), "+f"(d[3])
                 : "r"(a0), "r"(a1), "r"(a2), "r"(a3), "r"(b0), "r"(b1));
}

// ---------------------------------------------------------------------------
// Kernel A (HMMA): gx[t][b][c] = sum_k x[b][t][k] * w_x[k][c], fp32 output.
// CTA = (128 batch rows, 8 timesteps): w_x -> fp16 smem ONCE per CTA.
// 2-term x split (xh*wh + xl*wh). Direct float2 fragment stores.
// ---------------------------------------------------------------------------
#define WSTR 392
#define XSTR 40
#define GSM_WH 0
#define GSM_XH (32 * WSTR * 2)                  // 25088
#define GSM_XL (GSM_XH + HID * XSTR * 2)        // 35328
#define GSM_TOT (GSM_XL + HID * XSTR * 2)       // 45568

__global__ void __launch_bounds__(256, 2)
gx_kernel(const float* __restrict__ x,
          const float* __restrict__ w_x) {
    extern __shared__ char smem[];
    __half* sWH = (__half*)(smem + GSM_WH);
    __half* sXH = (__half*)(smem + GSM_XH);
    __half* sXL = (__half*)(smem + GSM_XL);
    const uint32_t sb = smem_u32(smem);

    const int tid = threadIdx.x;
    const int w   = tid >> 5;
    const int L   = tid & 31;
    const int b0  = blockIdx.x * 128;

    // ---- w_x -> fp16 smem, once per CTA (amortized over 8 timesteps) ----
    for (int idx = tid; idx < 3 * INP * HID; idx += 256) {
        int g = idx / (INP * HID);
        int k = (idx / HID) % INP;
        int u = idx & 127;
        sWH[k * WSTR + g * HID + u] = __float2half_rn(w_x[idx]);
    }
    for (int idx = tid; idx < 4 * C3; idx += 256) {
        int k = 28 + idx / C3, c = idx % C3;
        sWH[k * WSTR + c] = __ushort_as_half(0);
    }
    for (int idx = tid; idx < 128 * 4; idx += 256) {
        int r = idx >> 2, k = 28 + (idx & 3);
        sXH[r * XSTR + k] = __ushort_as_half(0);
        sXL[r * XSTR + k] = __ushort_as_half(0);
    }

    const uint32_t lrow = (L & 7) + ((L >> 3) & 1) * 8;
    const uint32_t lcol = (L >> 4) * 8;
    const uint32_t aXH = sb + GSM_XH + (uint32_t)((16 * w + lrow) * XSTR + lcol) * 2;
    const uint32_t aXL = sb + GSM_XL + (uint32_t)((16 * w + lrow) * XSTR + lcol) * 2;
    const uint32_t bWH = sb + GSM_WH + (uint32_t)(lrow * WSTR + lcol) * 2;

    const int rA = 16 * w + (L >> 2);
    const int cq = 2 * (L & 3);

    for (int tt = 0; tt < 8; ++tt) {
        const int t = blockIdx.y * 8 + tt;

        __syncthreads();   // prior iteration's x reads done (covers w fill on tt=0)
        for (int idx = tid; idx < 128 * 7; idx += 256) {
            int r = idx / 7, f = idx % 7;
            float4 v = *(const float4*)(x + ((size_t)(b0 + r) * TT + t) * INP + 4 * f);
            float vs[4] = {v.x, v.y, v.z, v.w};
#pragma unroll
            for (int j = 0; j < 4; ++j) {
                __half hi = __float2half_rn(vs[j]);
                __half lo = __float2half_rn(vs[j] - __half2float(hi));
                sXH[r * XSTR + 4 * f + j] = hi;
                sXL[r * XSTR + 4 * f + j] = lo;
            }
        }
        __syncthreads();

        uint32_t axh[2][4], axl[2][4];
#pragma unroll
        for (int kt = 0; kt < 2; ++kt) {
            ldsm4(axh[kt][0], axh[kt][1], axh[kt][2], axh[kt][3], aXH + kt * 32);
            ldsm4(axl[kt][0], axl[kt][1], axl[kt][2], axl[kt][3], aXL + kt * 32);
        }

        float* gxo = ((t < 256) ? g_gx_lo : g_gx_hi) + (size_t)(t & 255) * BB * C3;

#pragma unroll 1
        for (int ch = 0; ch < 6; ++ch) {
            float acc[8][4];
#pragma unroll
            for (int nb = 0; nb < 8; ++nb)
#pragma unroll
                for (int i = 0; i < 4; ++i) acc[nb][i] = 0.0f;

#pragma unroll
            for (int kt = 0; kt < 2; ++kt) {
#pragma unroll
                for (int grp = 0; grp < 4; ++grp) {
                    uint32_t off = (uint32_t)(kt * 16 * WSTR + ch * 64 + grp * 16) * 2;
                    uint32_t h0, h1, h2, h3;
                    ldsm4t(h0, h1, h2, h3, bWH + off);
                    float* a0 = acc[2 * grp];
                    float* a1 = acc[2 * grp + 1];
                    mma16816(a0, axh[kt][0], axh[kt][1], axh[kt][2], axh[kt][3], h0, h1);
                    mma16816(a0, axl[kt][0], axl[kt][1], axl[kt][2], axl[kt][3], h0, h1);
                    mma16816(a1, axh[kt][0], axh[kt][1], axh[kt][2], axh[kt][3], h2, h3);
                    mma16816(a1, axl[kt][0], axl[kt][1], axl[kt][2], axl[kt][3], h2, h3);
                }
            }

#pragma unroll
            for (int nb = 0; nb < 8; ++nb) {
                int c = ch * 64 + nb * 8 + cq;
                *(float2*)(gxo + (size_t)(b0 + rA) * C3 + c) =
                    make_float2(acc[nb][0], acc[nb][1]);
                *(float2*)(gxo + (size_t)(b0 + rA + 8) * C3 + c) =
                    make_float2(acc[nb][2], acc[nb][3]);
            }
        }
    }
}

// ---------------------------------------------------------------------------
// Kernel B: GRU on HMMA — verbatim R14 (best gru: 1.627 ms, rel_err 2e-4).
// 2-term split (wh*hh + wh*hl), batch-split software pipeline.
// ---------------------------------------------------------------------------
#define ASTR 136
#define AMAT (HID * ASTR)
#define BSTR 40
#define SM_B0 (3 * AMAT * 2)                    // 104448
#define SM_B1 (SM_B0 + HID * BSTR * 2)          // 114688
#define SM_TOT (SM_B1 + HID * BSTR * 2)         // 124928

__global__ void __launch_bounds__(256, 1)
gru_kernel(const float* __restrict__ w_h,
           const float* __restrict__ b_h,
           const float* __restrict__ b_x,
           const float* __restrict__ fc_w,
           const float* __restrict__ fc_b,
           float* __restrict__ out) {
    extern __shared__ char smem[];
    __half* sA = (__half*)smem;
    __half* sBhh = (__half*)(smem + SM_B0);
    __half* sBhl = (__half*)(smem + SM_B1);
    const uint32_t sb = smem_u32(smem);

    const int tid = threadIdx.x;
    const int w   = tid >> 5;
    const int L   = tid & 31;
    const int row0 = blockIdx.x * 32;
    const int uBase = 16 * w + (L >> 2);

    for (int g = 0; g < 3; ++g) {
        __half* ah = sA + g * AMAT;
        const float* wg = w_h + (size_t)g * HID * HID;
        for (int idx = tid; idx < HID * HID; idx += 256) {
            int k = idx >> 7, u = idx & 127;
            ah[u * ASTR + k] = __float2half_rn(wg[idx]);
        }
    }
    for (int i = tid; i < HID * BSTR; i += 256) {
        sBhh[i] = __ushort_as_half(0);
        sBhl[i] = __ushort_as_half(0);
    }
    __syncthreads();

    const uint32_t lrow = (L & 7) + ((L >> 3) & 1) * 8;
    const uint32_t lcol = (L >> 4) * 8;
    uint32_t aAddr[3];
#pragma unroll
    for (int m = 0; m < 3; ++m)
        aAddr[m] = sb + (uint32_t)(m * AMAT + (16 * w + lrow) * ASTR + lcol) * 2;
    const uint32_t bAddrHH = sb + SM_B0 + (lrow * BSTR + lcol) * 2;
    const uint32_t bAddrHL = sb + SM_B1 + (lrow * BSTR + lcol) * 2;

    float bhr[2], bhz[2], bhn[2], bxn[2];
#pragma unroll
    for (int ui = 0; ui < 2; ++ui) {
        int u = uBase + 8 * ui;
        bhr[ui] = b_h[u]           + b_x[u];
        bhz[ui] = b_h[HID + u]     + b_x[HID + u];
        bhn[ui] = b_h[2 * HID + u];
        bxn[ui] = b_x[2 * HID + u];
    }

    float hold0[2][4], hold1[2][4];
#pragma unroll
    for (int ui = 0; ui < 2; ++ui)
#pragma unroll
        for (int e = 0; e < 4; ++e) { hold0[ui][e] = 0.0f; hold1[ui][e] = 0.0f; }

    float acc0[3][2][4], acc1[3][2][4];
    float pg0[3][2][4], pg1[3][2][4];

#define LOAD_PG(PG, T, HF) do {                                               \
    const float* _b = ((T) < 256) ? g_gx_lo : g_gx_hi;                        \
    const float* _gp = _b + (size_t)((T) & 255) * BB * C3;                    \
    _Pragma("unroll")                                                         \
    for (int g = 0; g < 3; ++g)                                               \
        _Pragma("unroll")                                                     \
        for (int ui = 0; ui < 2; ++ui) {                                      \
            int u = uBase + 8 * ui;                                           \
            _Pragma("unroll")                                                 \
            for (int e = 0; e < 4; ++e) {                                     \
                int b = 16 * (HF) + 8 * (e >> 1) + 2 * (L & 3) + (e & 1);     \
                PG[g][ui][e] = __ldg(_gp + (size_t)(row0 + b) * C3 + g * HID + u); \
            }                                                                 \
        }                                                                     \
} while (0)

#define MMA_PHASE(ACC, HF) do {                                               \
    _Pragma("unroll")                                                         \
    for (int g = 0; g < 3; ++g)                                               \
        _Pragma("unroll")                                                     \
        for (int nb = 0; nb < 2; ++nb)                                        \
            _Pragma("unroll")                                                 \
            for (int i = 0; i < 4; ++i) ACC[g][nb][i] = 0.0f;                 \
    _Pragma("unroll")                                                         \
    for (int kt = 0; kt < 8; ++kt) {                                          \
        uint32_t bh0, bh1, bh2, bh3, bl0, bl1, bl2, bl3;                      \
        uint32_t boff = (uint32_t)(kt * 16 * BSTR * 2) + (HF) * 32;           \
        ldsm4t(bh0, bh1, bh2, bh3, bAddrHH + boff);                           \
        ldsm4t(bl0, bl1, bl2, bl3, bAddrHL + boff);                           \
        _Pragma("unroll")                                                     \
        for (int g = 0; g < 3; ++g) {                                         \
            uint32_t ah0, ah1, ah2, ah3;                                      \
            ldsm4(ah0, ah1, ah2, ah3, aAddr[g] + kt * 32);                    \
            mma16816(ACC[g][0], ah0, ah1, ah2, ah3, bh0, bh1);                \
            mma16816(ACC[g][0], ah0, ah1, ah2, ah3, bl0, bl1);                \
            mma16816(ACC[g][1], ah0, ah1, ah2, ah3, bh2, bh3);                \
            mma16816(ACC[g][1], ah0, ah1, ah2, ah3, bl2, bl3);                \
        }                                                                     \
    }                                                                         \
} while (0)

#define GATES_PHASE(ACC, PG, HOLD, HF, WRITE_B) do {                          \
    _Pragma("unroll")                                                         \
    for (int ui = 0; ui < 2; ++ui) {                                          \
        int u = uBase + 8 * ui;                                               \
        _Pragma("unroll")                                                     \
        for (int nb = 0; nb < 2; ++nb) {                                      \
            float hv[2];                                                      \
            _Pragma("unroll")                                                 \
            for (int q = 0; q < 2; ++q) {                                     \
                int e = 2 * nb + q;                                           \
                float ar = ACC[0][nb][2 * ui + q] + PG[0][ui][e] + bhr[ui];   \
                float az = ACC[1][nb][2 * ui + q] + PG[1][ui][e] + bhz[ui];   \
                float an = ACC[2][nb][2 * ui + q] + bhn[ui];                  \
                float rr = sig1(ar);                                          \
                float zz = sig1(az);                                          \
                float nn = tanh1(PG[2][ui][e] + bxn[ui] + rr * an);           \
                float h  = nn + zz * (HOLD[ui][e] - nn);                      \
                HOLD[ui][e] = h;                                              \
                hv[q] = h;                                                    \
            }                                                                 \
            if (WRITE_B) {                                                    \
                int b = 16 * (HF) + 8 * nb + 2 * (L & 3);                     \
                __half h0 = __float2half_rn(hv[0]);                           \
                __half h1 = __float2half_rn(hv[1]);                           \
                __half l0 = __float2half_rn(hv[0] - __half2float(h0));        \
                __half l1 = __float2half_rn(hv[1] - __half2float(h1));        \
                *(__half2*)(sBhh + u * BSTR + b) = __halves2half2(h0, h1);    \
                *(__half2*)(sBhl + u * BSTR + b) = __halves2half2(l0, l1);    \
            }                                                                 \
        }                                                                     \
    }                                                                         \
} while (0)

    LOAD_PG(pg0, 0, 0);

    for (int t = 0; t < TT; ++t) {
        MMA_PHASE(acc0, 0);                    // reads B0(t)
        if (t > 0) GATES_PHASE(acc1, pg1, hold1, 1, 1);   // writes B1(t)
        LOAD_PG(pg1, t, 1);
        __syncthreads();
        MMA_PHASE(acc1, 1);                    // reads B1(t)
        GATES_PHASE(acc0, pg0, hold0, 0, 1);   // writes B0(t+1)
        if (t + 1 < TT) LOAD_PG(pg0, t + 1, 0);
        __syncthreads();
    }
    GATES_PHASE(acc1, pg1, hold1, 1, 0);

    // ---- FC epilogue ----
    float* sH  = (float*)smem;
    float* sFW = (float*)smem + HID * 33;
#pragma unroll
    for (int ui = 0; ui < 2; ++ui) {
        int u = uBase + 8 * ui;
#pragma unroll
        for (int e = 0; e < 4; ++e) {
            int bq = 8 * (e >> 1) + 2 * (L & 3) + (e & 1);
            sH[u * 33 + bq]      = hold0[ui][e];
            sH[u * 33 + 16 + bq] = hold1[ui][e];
        }
    }
    for (int i = tid; i < HID * 10; i += 256) sFW[i] = fc_w[i];
    __syncthreads();
    for (int i = tid; i < 32 * 10; i += 256) {
        int lr = i / 10, col = i % 10;
        float s = fc_b[col];
#pragma unroll 8
        for (int uu = 0; uu < HID; ++uu)
            s += sH[uu * 33 + lr] * sFW[uu * 10 + col];
        out[(size_t)(row0 + lr) * 10 + col] = s;
    }
#undef LOAD_PG
#undef MMA_PHASE
#undef GATES_PHASE
}

extern "C" void kernel_launch(void* const* d_in, const int* in_sizes, int n_in,
                              void* d_out, int out_size) {
    const float* x    = (const float*)d_in[0];
    const float* w_x  = (const float*)d_in[1];
    const float* b_x  = (const float*)d_in[2];
    const float* w_h  = (const float*)d_in[3];
    const float* b_h  = (const float*)d_in[4];
    const float* fc_w = (const float*)d_in[5];
    const float* fc_b = (const float*)d_in[6];
    float* out = (float*)d_out;

    cudaFuncSetAttribute(gx_kernel,  cudaFuncAttributeMaxDynamicSharedMemorySize, GSM_TOT);
    cudaFuncSetAttribute(gru_kernel, cudaFuncAttributeMaxDynamicSharedMemorySize, SM_TOT);

    gx_kernel<<<dim3(32, TT / 8), 256, GSM_TOT>>>(x, w_x);
    gru_kernel<<<128, 256, SM_TOT>>>(w_h, b_h, b_x, fc_w, fc_b, out);
}

// round 17
// speedup vs baseline: 1.7696x; 1.5233x over previous
#include <cuda_runtime.h>
#include <cuda_fp16.h>
#include <cstdint>
#include <cstddef>

#define HID 128
#define C3  384
#define TT  512
#define BB  4096
#define INP 28

static __device__ __forceinline__ float sig1(float x) {
    float e = __expf(-x);
    return __fdividef(1.0f, 1.0f + e);
}
static __device__ __forceinline__ float tanh1(float x) {
    float e = __expf(2.0f * x);
    return 1.0f - __fdividef(2.0f, e + 1.0f);
}
static __device__ __forceinline__ uint32_t smem_u32(const void* p) {
    uint32_t a;
    asm("{ .reg .u64 t; cvta.to.shared.u64 t, %1; cvt.u32.u64 %0, t; }"
        : "=r"(a) : "l"(p));
    return a;
}
static __device__ __forceinline__ void ldsm4(uint32_t& r0, uint32_t& r1,
                                             uint32_t& r2, uint32_t& r3, uint32_t a) {
    asm volatile("ldmatrix.sync.aligned.m8n8.x4.shared.b16 {%0,%1,%2,%3}, [%4];"
                 : "=r"(r0), "=r"(r1), "=r"(r2), "=r"(r3) : "r"(a));
}
static __device__ __forceinline__ void ldsm4t(uint32_t& r0, uint32_t& r1,
                                              uint32_t& r2, uint32_t& r3, uint32_t a) {
    asm volatile("ldmatrix.sync.aligned.m8n8.x4.trans.shared.b16 {%0,%1,%2,%3}, [%4];"
                 : "=r"(r0), "=r"(r1), "=r"(r2), "=r"(r3) : "r"(a));
}
static __device__ __forceinline__ void mma16816(float* d,
        uint32_t a0, uint32_t a1, uint32_t a2, uint32_t a3,
        uint32_t b0, uint32_t b1) {
    asm volatile("mma.sync.aligned.m16n8k16.row.col.f32.f16.f16.f32 "
                 "{%0,%1,%2,%3},{%4,%5,%6,%7},{%8,%9},{%0,%1,%2,%3};"
                 : "+f"(d[0]), "+f"(d[1]), "+f"(d[2]), "+f"(d[3])
                 : "r"(a0), "r"(a1), "r"(a2), "r"(a3), "r"(b0), "r"(b1));
}

// ---------------------------------------------------------------------------
// Fused GRU: input projection x(t)*w_x folded into the recurrent HMMA step.
// 128 CTAs x 32 batch rows, 256 threads / 8 warps. Per step per warp:
//   h-mma: 3 gates x 2 nb x 2 terms (hh,hl) x 8 kt = 96
//   x-mma: 3 gates x 2 nb x 2 terms (xh,xl) x 2 kt = 24  (K=28 padded to 32)
// n-gate's x-part goes to a separate accumulator (needed outside r*gh_n).
// w_x A-fragments register-resident. Batch-split software pipeline (R14).
// ---------------------------------------------------------------------------
#define ASTR 136
#define AMAT (HID * ASTR)
#define BSTR 40
#define SM_B0   (3 * AMAT * 2)                  // 104448  Bh_hh
#define SM_B1   (SM_B0 + HID * BSTR * 2)        // 114688  Bh_hl
#define SM_XA   (SM_B1 + HID * BSTR * 2)        // 124928  w_x [3][128u][40k]
#define SM_XBH  (SM_XA + 3 * HID * BSTR * 2)    // 155648  x hi [2][32k][40b]
#define SM_XBL  (SM_XBH + 2 * 32 * BSTR * 2)    // 160768  x lo
#define SM_TOT  (SM_XBL + 2 * 32 * BSTR * 2)    // 165888

__global__ void __launch_bounds__(256, 1)
gru_kernel(const float* __restrict__ x,
           const float* __restrict__ w_x,
           const float* __restrict__ b_x,
           const float* __restrict__ w_h,
           const float* __restrict__ b_h,
           const float* __restrict__ fc_w,
           const float* __restrict__ fc_b,
           float* __restrict__ out) {
    extern __shared__ char smem[];
    __half* sA   = (__half*)smem;
    __half* sBhh = (__half*)(smem + SM_B0);
    __half* sBhl = (__half*)(smem + SM_B1);
    __half* sXA  = (__half*)(smem + SM_XA);
    __half* sXh  = (__half*)(smem + SM_XBH);
    __half* sXl  = (__half*)(smem + SM_XBL);
    const uint32_t sb = smem_u32(smem);

    const int tid = threadIdx.x;
    const int w   = tid >> 5;
    const int L   = tid & 31;
    const int row0 = blockIdx.x * 32;
    const int uBase = 16 * w + (L >> 2);

    // ---- w_h -> fp16 smem A matrices ----
    for (int g = 0; g < 3; ++g) {
        __half* ah = sA + g * AMAT;
        const float* wg = w_h + (size_t)g * HID * HID;
        for (int idx = tid; idx < HID * HID; idx += 256) {
            int k = idx >> 7, u = idx & 127;
            ah[u * ASTR + k] = __float2half_rn(wg[idx]);
        }
    }
    // ---- w_x -> fp16 smem [g][u][k], k padded 28->32 ----
    for (int idx = tid; idx < 3 * INP * HID; idx += 256) {
        int g = idx / (INP * HID);
        int k = (idx / HID) % INP;
        int u = idx & 127;
        sXA[(g * HID + u) * BSTR + k] = __float2half_rn(w_x[idx]);
    }
    for (int idx = tid; idx < 3 * HID * 4; idx += 256) {
        int g = idx / (HID * 4);
        int u = (idx >> 2) & 127;
        int k = 28 + (idx & 3);
        sXA[(g * HID + u) * BSTR + k] = __ushort_as_half(0);
    }
    // ---- zero h B tiles + x pad rows (k=28..31, both buffers) ----
    for (int i = tid; i < HID * BSTR; i += 256) {
        sBhh[i] = __ushort_as_half(0);
        sBhl[i] = __ushort_as_half(0);
    }
    for (int i = tid; i < 2 * 4 * 32; i += 256) {
        int buf = i >> 7;
        int k   = 28 + ((i >> 5) & 3);
        int b   = i & 31;
        sXh[buf * 32 * BSTR + k * BSTR + b] = __ushort_as_half(0);
        sXl[buf * 32 * BSTR + k * BSTR + b] = __ushort_as_half(0);
    }
    // ---- stage x(0) into buffer 0 ----
#pragma unroll
    for (int i = 0; i < 4; ++i) {
        int idx = tid + 256 * i;
        if (idx < 32 * INP) {
            int r = idx / INP, k = idx % INP;
            float v = __ldg(x + ((size_t)(row0 + r) * TT + 0) * INP + k);
            __half hi = __float2half_rn(v);
            __half lo = __float2half_rn(v - __half2float(hi));
            sXh[k * BSTR + r] = hi;
            sXl[k * BSTR + r] = lo;
        }
    }
    __syncthreads();

    const uint32_t lrow = (L & 7) + ((L >> 3) & 1) * 8;
    const uint32_t lcol = (L >> 4) * 8;
    uint32_t aAddr[3];
#pragma unroll
    for (int m = 0; m < 3; ++m)
        aAddr[m] = sb + (uint32_t)(m * AMAT + (16 * w + lrow) * ASTR + lcol) * 2;
    const uint32_t bAddrHH = sb + SM_B0 + (lrow * BSTR + lcol) * 2;
    const uint32_t bAddrHL = sb + SM_B1 + (lrow * BSTR + lcol) * 2;
    const uint32_t xAddrH  = sb + SM_XBH + (lrow * BSTR + lcol) * 2;
    const uint32_t xAddrL  = sb + SM_XBL + (lrow * BSTR + lcol) * 2;

    // ---- w_x A-fragments: register-resident for the whole kernel ----
    uint32_t axw[3][2][4];
#pragma unroll
    for (int g = 0; g < 3; ++g) {
        uint32_t base = sb + SM_XA + (uint32_t)((g * HID + 16 * w + lrow) * BSTR + lcol) * 2;
#pragma unroll
        for (int kt = 0; kt < 2; ++kt)
            ldsm4(axw[g][kt][0], axw[g][kt][1], axw[g][kt][2], axw[g][kt][3],
                  base + kt * 32);
    }

    float bhr[2], bhz[2], bhn[2], bxn[2];
#pragma unroll
    for (int ui = 0; ui < 2; ++ui) {
        int u = uBase + 8 * ui;
        bhr[ui] = b_h[u]           + b_x[u];
        bhz[ui] = b_h[HID + u]     + b_x[HID + u];
        bhn[ui] = b_h[2 * HID + u];
        bxn[ui] = b_x[2 * HID + u];
    }

    float hold0[2][4], hold1[2][4];
#pragma unroll
    for (int ui = 0; ui < 2; ++ui)
#pragma unroll
        for (int e = 0; e < 4; ++e) { hold0[ui][e] = 0.0f; hold1[ui][e] = 0.0f; }

    float acc0[3][2][4], acc1[3][2][4];
    float axn0[2][4],    axn1[2][4];

#define MMA_PHASE(ACC, AXN, HF, XOFF) do {                                    \
    _Pragma("unroll")                                                         \
    for (int g = 0; g < 3; ++g)                                               \
        _Pragma("unroll")                                                     \
        for (int nb = 0; nb < 2; ++nb)                                        \
            _Pragma("unroll")                                                 \
            for (int i = 0; i < 4; ++i) ACC[g][nb][i] = 0.0f;                 \
    _Pragma("unroll")                                                         \
    for (int nb = 0; nb < 2; ++nb)                                            \
        _Pragma("unroll")                                                     \
        for (int i = 0; i < 4; ++i) AXN[nb][i] = 0.0f;                        \
    /* x projection: K=32 (2 kt), 2-term x split, w_x frags in regs */        \
    _Pragma("unroll")                                                         \
    for (int xk = 0; xk < 2; ++xk) {                                          \
        uint32_t xb0, xb1, xb2, xb3, xl0, xl1, xl2, xl3;                      \
        uint32_t xo = (uint32_t)(XOFF) + (uint32_t)(xk * 16 * BSTR * 2)       \
                      + (HF) * 32;                                            \
        ldsm4t(xb0, xb1, xb2, xb3, xAddrH + xo);                              \
        ldsm4t(xl0, xl1, xl2, xl3, xAddrL + xo);                              \
        _Pragma("unroll")                                                     \
        for (int g = 0; g < 3; ++g) {                                         \
            float* t0 = (g < 2) ? ACC[g][0] : AXN[0];                         \
            float* t1 = (g < 2) ? ACC[g][1] : AXN[1];                         \
            mma16816(t0, axw[g][xk][0], axw[g][xk][1], axw[g][xk][2],         \
                     axw[g][xk][3], xb0, xb1);                                \
            mma16816(t0, axw[g][xk][0], axw[g][xk][1], axw[g][xk][2],         \
                     axw[g][xk][3], xl0, xl1);                                \
            mma16816(t1, axw[g][xk][0], axw[g][xk][1], axw[g][xk][2],         \
                     axw[g][xk][3], xb2, xb3);                                \
            mma16816(t1, axw[g][xk][0], axw[g][xk][1], axw[g][xk][2],         \
                     axw[g][xk][3], xl2, xl3);                                \
        }                                                                     \
    }                                                                         \
    /* recurrent matvec: K=128 (8 kt), 2-term h split */                      \
    _Pragma("unroll")                                                         \
    for (int kt = 0; kt < 8; ++kt) {                                          \
        uint32_t bh0, bh1, bh2, bh3, bl0, bl1, bl2, bl3;                      \
        uint32_t boff = (uint32_t)(kt * 16 * BSTR * 2) + (HF) * 32;           \
        ldsm4t(bh0, bh1, bh2, bh3, bAddrHH + boff);                           \
        ldsm4t(bl0, bl1, bl2, bl3, bAddrHL + boff);                           \
        _Pragma("unroll")                                                     \
        for (int g = 0; g < 3; ++g) {                                         \
            uint32_t ah0, ah1, ah2, ah3;                                      \
            ldsm4(ah0, ah1, ah2, ah3, aAddr[g] + kt * 32);                    \
            mma16816(ACC[g][0], ah0, ah1, ah2, ah3, bh0, bh1);                \
            mma16816(ACC[g][0], ah0, ah1, ah2, ah3, bl0, bl1);                \
            mma16816(ACC[g][1], ah0, ah1, ah2, ah3, bh2, bh3);                \
            mma16816(ACC[g][1], ah0, ah1, ah2, ah3, bl2, bl3);                \
        }                                                                     \
    }                                                                         \
} while (0)

#define GATES_PHASE(ACC, AXN, HOLD, HF, WRITE_B) do {                         \
    _Pragma("unroll")                                                         \
    for (int ui = 0; ui < 2; ++ui) {                                          \
        int u = uBase + 8 * ui;                                               \
        _Pragma("unroll")                                                     \
        for (int nb = 0; nb < 2; ++nb) {                                      \
            float hv[2];                                                      \
            _Pragma("unroll")                                                 \
            for (int q = 0; q < 2; ++q) {                                     \
                int e = 2 * nb + q;                                           \
                float ar = ACC[0][nb][2 * ui + q] + bhr[ui];                  \
                float az = ACC[1][nb][2 * ui + q] + bhz[ui];                  \
                float an = ACC[2][nb][2 * ui + q] + bhn[ui];                  \
                float gn = AXN[nb][2 * ui + q] + bxn[ui];                     \
                float rr = sig1(ar);                                          \
                float zz = sig1(az);                                          \
                float nn = tanh1(gn + rr * an);                               \
                float h  = nn + zz * (HOLD[ui][e] - nn);                      \
                HOLD[ui][e] = h;                                              \
                hv[q] = h;                                                    \
            }                                                                 \
            if (WRITE_B) {                                                    \
                int b = 16 * (HF) + 8 * nb + 2 * (L & 3);                     \
                __half h0 = __float2half_rn(hv[0]);                           \
                __half h1 = __float2half_rn(hv[1]);                           \
                __half l0 = __float2half_rn(hv[0] - __half2float(h0));        \
                __half l1 = __float2half_rn(hv[1] - __half2float(h1));        \
                *(__half2*)(sBhh + u * BSTR + b) = __halves2half2(h0, h1);    \
                *(__half2*)(sBhl + u * BSTR + b) = __halves2half2(l0, l1);    \
            }                                                                 \
        }                                                                     \
    }                                                                         \
} while (0)

    for (int t = 0; t < TT; ++t) {
        const int xoff = (t & 1) * (32 * BSTR * 2);   // x(t) buffer, bytes

        // issue x(t+1) loads early (latency hidden under the whole step)
        float xv[4];
        if (t + 1 < TT) {
#pragma unroll
            for (int i = 0; i < 4; ++i) {
                int idx = tid + 256 * i;
                if (idx < 32 * INP) {
                    int r = idx / INP, k = idx % INP;
                    xv[i] = __ldg(x + ((size_t)(row0 + r) * TT + (t + 1)) * INP + k);
                }
            }
        }

        MMA_PHASE(acc0, axn0, 0, xoff);                  // reads Bh0(t), x(t)
        if (t > 0) GATES_PHASE(acc1, axn1, hold1, 1, 1); // writes Bh1(t)
        __syncthreads();
        MMA_PHASE(acc1, axn1, 1, xoff);                  // reads Bh1(t), x(t)
        GATES_PHASE(acc0, axn0, hold0, 0, 1);            // writes Bh0(t+1)

        // convert + store x(t+1) into the other buffer
        if (t + 1 < TT) {
            const int nbuf = ((t + 1) & 1) * 32 * BSTR;
#pragma unroll
            for (int i = 0; i < 4; ++i) {
                int idx = tid + 256 * i;
                if (idx < 32 * INP) {
                    int r = idx / INP, k = idx % INP;
                    __half hi = __float2half_rn(xv[i]);
                    __half lo = __float2half_rn(xv[i] - __half2float(hi));
                    sXh[nbuf + k * BSTR + r] = hi;
                    sXl[nbuf + k * BSTR + r] = lo;
                }
            }
        }
        __syncthreads();
    }
    GATES_PHASE(acc1, axn1, hold1, 1, 0);   // final half-1 state

    // ---- FC epilogue (reuses dead A region) ----
    float* sH  = (float*)smem;              // [128][33]
    float* sFW = (float*)smem + HID * 33;
#pragma unroll
    for (int ui = 0; ui < 2; ++ui) {
        int u = uBase + 8 * ui;
#pragma unroll
        for (int e = 0; e < 4; ++e) {
            int bq = 8 * (e >> 1) + 2 * (L & 3) + (e & 1);
            sH[u * 33 + bq]      = hold0[ui][e];
            sH[u * 33 + 16 + bq] = hold1[ui][e];
        }
    }
    for (int i = tid; i < HID * 10; i += 256) sFW[i] = fc_w[i];
    __syncthreads();
    for (int i = tid; i < 32 * 10; i += 256) {
        int lr = i / 10, col = i % 10;
        float s = fc_b[col];
#pragma unroll 8
        for (int uu = 0; uu < HID; ++uu)
            s += sH[uu * 33 + lr] * sFW[uu * 10 + col];
        out[(size_t)(row0 + lr) * 10 + col] = s;
    }
#undef MMA_PHASE
#undef GATES_PHASE
}

extern "C" void kernel_launch(void* const* d_in, const int* in_sizes, int n_in,
                              void* d_out, int out_size) {
    const float* x    = (const float*)d_in[0];
    const float* w_x  = (const float*)d_in[1];
    const float* b_x  = (const float*)d_in[2];
    const float* w_h  = (const float*)d_in[3];
    const float* b_h  = (const float*)d_in[4];
    const float* fc_w = (const float*)d_in[5];
    const float* fc_b = (const float*)d_in[6];
    float* out = (float*)d_out;

    cudaFuncSetAttribute(gru_kernel, cudaFuncAttributeMaxDynamicSharedMemorySize, SM_TOT);
    gru_kernel<<<128, 256, SM_TOT>>>(x, w_x, b_x, w_h, b_h, fc_w, fc_b, out);
}